// round 4
// baseline (speedup 1.0000x reference)
#include <cuda_runtime.h>
#include <cuda_bf16.h>

// out = x > 0 ? 0.9*x + 0.1*tanh(x) : 0.5*tanh(x)
// Elementwise over 8192*8192 fp32. Pure HBM-streaming kernel.
//
// R3: 8 float4 per thread, all loads front-batched (MLP=8), streaming
// cache hints. Strided partitioning keeps per-warp coalescing perfect.

#define VPT 8  // float4s per thread

__device__ __forceinline__ float act(float x) {
    float t = tanhf(x);
    return (x > 0.0f) ? fmaf(x, 0.9f, t * 0.1f) : (t * 0.5f);
}

__device__ __forceinline__ float4 act4(float4 v) {
    float4 r;
    r.x = act(v.x);
    r.y = act(v.y);
    r.z = act(v.z);
    r.w = act(v.w);
    return r;
}

// Fast path: n4 = VPT * total_threads exactly.
__global__ void __launch_bounds__(256)
activation_vec4x8_kernel(const float4* __restrict__ in, float4* __restrict__ out,
                         int stride /* = total threads = n4/VPT */) {
    int i = blockIdx.x * blockDim.x + threadIdx.x;

    float4 v[VPT];
#pragma unroll
    for (int k = 0; k < VPT; k++)
        v[k] = __ldcs(&in[i + k * stride]);

#pragma unroll
    for (int k = 0; k < VPT; k++)
        __stcs(&out[i + k * stride], act4(v[k]));
}

// Generic path (bounds-checked grid-stride).
__global__ void __launch_bounds__(256)
activation_vec4_kernel(const float4* __restrict__ in, float4* __restrict__ out, int n4) {
    int i = blockIdx.x * blockDim.x + threadIdx.x;
    int stride = gridDim.x * blockDim.x;
    for (; i < n4; i += stride) {
        __stcs(&out[i], act4(__ldcs(&in[i])));
    }
}

__global__ void __launch_bounds__(256)
activation_tail_kernel(const float* __restrict__ in, float* __restrict__ out,
                       int start, int n) {
    int i = start + blockIdx.x * blockDim.x + threadIdx.x;
    if (i < n) out[i] = act(in[i]);
}

extern "C" void kernel_launch(void* const* d_in, const int* in_sizes, int n_in,
                              void* d_out, int out_size) {
    const float* x = (const float*)d_in[0];
    float* out = (float*)d_out;
    int n = in_sizes[0];

    const int threads = 256;
    int n4 = n / 4;

    if (n4 > 0 && (n4 % (VPT * threads)) == 0) {
        int total_threads = n4 / VPT;
        int blocks = total_threads / threads;
        activation_vec4x8_kernel<<<blocks, threads>>>(
            (const float4*)x, (float4*)out, total_threads);
    } else if (n4 > 0) {
        int blocks = (n4 + threads - 1) / threads;
        if (blocks > 65535 * 2) blocks = 65535 * 2;
        activation_vec4_kernel<<<blocks, threads>>>(
            (const float4*)x, (float4*)out, n4);
    }

    int rem = n - n4 * 4;
    if (rem > 0) {
        activation_tail_kernel<<<1, 256>>>(x, out, n4 * 4, n);
    }
}

// round 5
// speedup vs baseline: 1.0004x; 1.0004x over previous
#include <cuda_runtime.h>
#include <cuda_bf16.h>

// out = x > 0 ? 0.9*x + 0.1*tanh(x) : 0.5*tanh(x)
// Elementwise over 8192*8192 fp32. Pure HBM-streaming kernel.
//
// R4: back to VPT=4 (best occupancy/MLP balance), MUFU.TANH via
// tanh.approx.f32 to collapse the per-element compute chain to 1 instr.

#define VPT 4  // float4s per thread

__device__ __forceinline__ float fast_tanh(float x) {
    float y;
    asm("tanh.approx.f32 %0, %1;" : "=f"(y) : "f"(x));
    return y;
}

__device__ __forceinline__ float act(float x) {
    float t = fast_tanh(x);
    return (x > 0.0f) ? fmaf(x, 0.9f, t * 0.1f) : (t * 0.5f);
}

__device__ __forceinline__ float4 act4(float4 v) {
    float4 r;
    r.x = act(v.x);
    r.y = act(v.y);
    r.z = act(v.z);
    r.w = act(v.w);
    return r;
}

// Fast path: n4 = VPT * total_threads exactly.
__global__ void __launch_bounds__(256)
activation_vec4x4_kernel(const float4* __restrict__ in, float4* __restrict__ out,
                         int stride /* = total threads = n4/VPT */) {
    int i = blockIdx.x * blockDim.x + threadIdx.x;

    float4 v[VPT];
#pragma unroll
    for (int k = 0; k < VPT; k++)
        v[k] = __ldcs(&in[i + k * stride]);

#pragma unroll
    for (int k = 0; k < VPT; k++)
        __stcs(&out[i + k * stride], act4(v[k]));
}

// Generic path (bounds-checked grid-stride).
__global__ void __launch_bounds__(256)
activation_vec4_kernel(const float4* __restrict__ in, float4* __restrict__ out, int n4) {
    int i = blockIdx.x * blockDim.x + threadIdx.x;
    int stride = gridDim.x * blockDim.x;
    for (; i < n4; i += stride) {
        __stcs(&out[i], act4(__ldcs(&in[i])));
    }
}

__global__ void __launch_bounds__(256)
activation_tail_kernel(const float* __restrict__ in, float* __restrict__ out,
                       int start, int n) {
    int i = start + blockIdx.x * blockDim.x + threadIdx.x;
    if (i < n) out[i] = act(in[i]);
}

extern "C" void kernel_launch(void* const* d_in, const int* in_sizes, int n_in,
                              void* d_out, int out_size) {
    const float* x = (const float*)d_in[0];
    float* out = (float*)d_out;
    int n = in_sizes[0];

    const int threads = 256;
    int n4 = n / 4;

    if (n4 > 0 && (n4 % (VPT * threads)) == 0) {
        int total_threads = n4 / VPT;
        int blocks = total_threads / threads;
        activation_vec4x4_kernel<<<blocks, threads>>>(
            (const float4*)x, (float4*)out, total_threads);
    } else if (n4 > 0) {
        int blocks = (n4 + threads - 1) / threads;
        if (blocks > 65535 * 2) blocks = 65535 * 2;
        activation_vec4_kernel<<<blocks, threads>>>(
            (const float4*)x, (float4*)out, n4);
    }

    int rem = n - n4 * 4;
    if (rem > 0) {
        activation_tail_kernel<<<1, 256>>>(x, out, n4 * 4, n);
    }
}